// round 6
// baseline (speedup 1.0000x reference)
#include <cuda_runtime.h>
#include <math.h>

// KAN network: 3 layers, BATCH=256, dims 256->512->256->128, GRID=5
// Factorization: sum_k w_k * exp(-s*|a-g_k|) = exp(-s*a)*P_m + exp(s*a)*Q_m
//   m = #{k : g_k <= a}; P/Q prefix/suffix tables per (o,i), 8 floats each.
// R6: conflict-free i4-major smem layouts (av 4wf->2wf), IC=64 for big layers
//     (half the barriers), split-K 8 for L2, vectorized epilogues.

#define BB 256
#define GG 5

#define L0_IN 256
#define L0_OUT 512
#define L1_IN 512
#define L1_OUT 256
#define L2_IN 256
#define L2_OUT 128

static __device__ __constant__ float kLOG2E = 1.4426950408889634f;

// ---- scratch (device globals; no allocation allowed) ----
__device__ __align__(16) float gT0[L0_OUT * L0_IN * 8];
__device__ float gS0[L0_OUT * L0_IN];
__device__ __align__(16) float gT1[L1_OUT * L1_IN * 8];
__device__ float gS1[L1_OUT * L1_IN];
__device__ __align__(16) float gT2[L2_OUT * L2_IN * 8];
__device__ float gS2[L2_OUT * L2_IN];

__device__ float gA0[BB * L0_IN];
__device__ unsigned char gM0[BB * L0_IN];
__device__ float gA1[BB * L1_IN];
__device__ unsigned char gM1[BB * L1_IN];
__device__ float gA2[BB * L2_IN];
__device__ unsigned char gM2[BB * L2_IN];

// split-K partial sums: [split][b][o], max 256K floats = 1MB
__device__ float gPart[4 * BB * 512];

__device__ __forceinline__ float ex2f(float x) {
    float y;
    asm("ex2.approx.ftz.f32 %0, %1;" : "=f"(y) : "f"(x));
    return y;
}

__device__ __forceinline__ unsigned char moff_of(float a) {
    int m = (int)(a >= -0.5f) + (int)(a >= 0.f) + (int)(a >= 0.5f);
    return (unsigned char)(m * 8);  // byte offset into 8-float table entry
}

// per-(o,i) table: T[idx*8 + m*2] = P_{m+1}, T[idx*8 + m*2 + 1] = Q_{m+1}
__device__ __forceinline__ void precompute_one(
    int idx, const float* __restrict__ w, const float* __restrict__ s,
    const float* __restrict__ g, float* __restrict__ T, float* __restrict__ S2) {
    float s2 = __ldg(&s[idx]) * kLOG2E;
    S2[idx] = s2;
    float gk[GG], wk[GG];
#pragma unroll
    for (int k = 0; k < GG; k++) {
        gk[k] = __ldg(&g[k]);
        wk[k] = __ldg(&w[idx * GG + k]);
    }
    float q[GG + 1];
    q[GG] = 0.f;
#pragma unroll
    for (int k = GG - 1; k >= 0; k--)
        q[k] = q[k + 1] + wk[k] * ex2f(-s2 * gk[k]);
    float P = 0.f;
#pragma unroll
    for (int m = 1; m <= 4; m++) {
        P += wk[m - 1] * ex2f(s2 * gk[m - 1]);
        T[idx * 8 + (m - 1) * 2 + 0] = P;
        T[idx * 8 + (m - 1) * 2 + 1] = q[m];
    }
}

// ---- fused setup: 3 table precomputes + input activation ----
#define N_T0 (L0_OUT * L0_IN)
#define N_T1 (L1_OUT * L1_IN)
#define N_T2 (L2_OUT * L2_IN)
#define N_ACT (BB * L0_IN)
#define SETUP_TOTAL (N_T0 + N_T1 + N_T2 + N_ACT)

__global__ __launch_bounds__(256) void setup_kernel(
    const float* __restrict__ x,
    const float* __restrict__ w0, const float* __restrict__ s0, const float* __restrict__ g0,
    const float* __restrict__ w1, const float* __restrict__ s1, const float* __restrict__ g1,
    const float* __restrict__ w2, const float* __restrict__ s2, const float* __restrict__ g2,
    float* __restrict__ T0, float* __restrict__ S20,
    float* __restrict__ T1, float* __restrict__ S21,
    float* __restrict__ T2, float* __restrict__ S22,
    float* __restrict__ A0, unsigned char* __restrict__ M0) {
    int gid = blockIdx.x * 256 + threadIdx.x;
    if (gid < N_T0) {
        precompute_one(gid, w0, s0, g0, T0, S20);
    } else if (gid < N_T0 + N_T1) {
        precompute_one(gid - N_T0, w1, s1, g1, T1, S21);
    } else if (gid < N_T0 + N_T1 + N_T2) {
        precompute_one(gid - N_T0 - N_T1, w2, s2, g2, T2, S22);
    } else {
        int i = gid - N_T0 - N_T1 - N_T2;
        float a = tanhf(__ldg(&x[i]));
        A0[i] = a;
        M0[i] = moff_of(a);
    }
}

// ---- layer kernel (split-K): writes partial sum to P[split][b][o] ----
// Tile: BT=16 batch x OT=16 out, 256 threads, IC i-chunk, grid.z = SPLIT.
// i4-major smem layouts: av/sv reads hit consecutive addresses (no conflicts).
template <int IN, int OUT, int SPLIT, int IC>
__global__ __launch_bounds__(256, 5) void layer_kernel(
    const float* __restrict__ A, const unsigned char* __restrict__ M,
    const float* __restrict__ T, const float* __restrict__ S2,
    float* __restrict__ P) {
    constexpr int BT = 16, OT = 16;
    constexpr int ILEN = IN / SPLIT;
    constexpr int NQ = IC / 4;          // float4 quads per row
    constexpr int MW = NQ + 1;          // padded m-word stride

    __shared__ float4 sA4[NQ][BT];
    __shared__ float4 sS4[NQ][OT];
    __shared__ unsigned int sMW[BT][MW];
    __shared__ __align__(16) float sT[IC][OT][8];

    const int tid = threadIdx.x;
    const int bl = tid & 15;
    const int ol = tid >> 4;
    const int b0 = blockIdx.y * BT;
    const int o0 = blockIdx.x * OT;
    const int ibase = blockIdx.z * ILEN;

    float accP0 = 0.f, accP1 = 0.f, accQ0 = 0.f, accQ1 = 0.f;

#pragma unroll 1
    for (int ic = 0; ic < ILEN / IC; ic++) {
        const int i0 = ibase + ic * IC;
        __syncthreads();
        if (tid < 128) {
            // stage A as float4 into i4-major layout + packed m words
#pragma unroll
            for (int k = 0; k < IC / 32; k++) {
                int v = tid + k * 128;              // < 4*IC
                int bb = v / NQ, iq = v % NQ;
                sA4[iq][bb] = *(const float4*)&A[(b0 + bb) * IN + i0 + iq * 4];
                sMW[bb][iq] = ((const unsigned int*)(M + (b0 + bb) * IN + i0))[iq];
            }
        } else {
#pragma unroll
            for (int k = 0; k < IC / 32; k++) {
                int v = (tid - 128) + k * 128;
                int oo = v / NQ, iq = v % NQ;
                sS4[iq][oo] = *(const float4*)&S2[(o0 + oo) * IN + i0 + iq * 4];
            }
        }
        // stage T: OT*IC*2 float4s, gmem-coalesced (part fastest, then ii, then oo)
#pragma unroll
        for (int k = 0; k < IC / 8; k++) {
            int v = tid + k * 256;                  // < OT*IC*2
            int oo = v / (IC * 2);
            int ii = (v >> 1) & (IC - 1);
            int part = v & 1;
            *(float4*)&sT[ii][oo][part * 4] =
                *(const float4*)&T[(((o0 + oo) * IN + i0 + ii) << 3) + part * 4];
        }
        __syncthreads();

        const unsigned int* sMrow = sMW[bl];
        const char* tbase = (const char*)&sT[0][ol][0];

#pragma unroll
        for (int i4 = 0; i4 < NQ; i4++) {
            float4 av = sA4[i4][bl];
            float4 sv = sS4[i4][ol];
            unsigned int mw = sMrow[i4];
            const char* tb = tbase + i4 * 4 * (OT * 8 * 4);

            {
                unsigned int mo = mw & 0xFFu;
                float2 pq = *(const float2*)(tb + mo);
                float t = av.x * sv.x;
                accP0 = fmaf(ex2f(-t), pq.x, accP0);
                accQ0 = fmaf(ex2f(t), pq.y, accQ0);
            }
            {
                unsigned int mo = (mw >> 8) & 0xFFu;
                float2 pq = *(const float2*)(tb + (OT * 8 * 4) + mo);
                float t = av.y * sv.y;
                accP1 = fmaf(ex2f(-t), pq.x, accP1);
                accQ1 = fmaf(ex2f(t), pq.y, accQ1);
            }
            {
                unsigned int mo = (mw >> 16) & 0xFFu;
                float2 pq = *(const float2*)(tb + 2 * (OT * 8 * 4) + mo);
                float t = av.z * sv.z;
                accP0 = fmaf(ex2f(-t), pq.x, accP0);
                accQ0 = fmaf(ex2f(t), pq.y, accQ0);
            }
            {
                unsigned int mo = mw >> 24;
                float2 pq = *(const float2*)(tb + 3 * (OT * 8 * 4) + mo);
                float t = av.w * sv.w;
                accP1 = fmaf(ex2f(-t), pq.x, accP1);
                accQ1 = fmaf(ex2f(t), pq.y, accQ1);
            }
        }
    }

    P[(blockIdx.z * BB + b0 + bl) * OUT + o0 + ol] =
        (accP0 + accP1) + (accQ0 + accQ1);
}

// ---- epilogue: sum SPLIT partials + bias, activation (vectorized x4) ----
template <int OUT, int SPLIT, bool LAST>
__global__ __launch_bounds__(256) void epi_kernel(
    const float* __restrict__ P, const float* __restrict__ bias,
    float* __restrict__ Anext, unsigned char* __restrict__ Mnext,
    float* __restrict__ out) {
    int idx4 = blockIdx.x * 256 + threadIdx.x;   // float4 index, < BB*OUT/4
    int o4 = idx4 & (OUT / 4 - 1);
    float4 y = *(const float4*)&bias[o4 * 4];
#pragma unroll
    for (int s = 0; s < SPLIT; s++) {
        float4 p = *(const float4*)&P[s * BB * OUT + idx4 * 4];
        y.x += p.x; y.y += p.y; y.z += p.z; y.w += p.w;
    }
    if (LAST) {
        float4 r;
        r.x = tanhf(y.x); r.y = tanhf(y.y); r.z = tanhf(y.z); r.w = tanhf(y.w);
        *(float4*)&out[idx4 * 4] = r;
    } else {
        float4 a;
        a.x = (y.x > 0.f) ? tanhf(y.x) : 0.f;
        a.y = (y.y > 0.f) ? tanhf(y.y) : 0.f;
        a.z = (y.z > 0.f) ? tanhf(y.z) : 0.f;
        a.w = (y.w > 0.f) ? tanhf(y.w) : 0.f;
        *(float4*)&Anext[idx4 * 4] = a;
        unsigned int mp = (unsigned int)moff_of(a.x)
                        | ((unsigned int)moff_of(a.y) << 8)
                        | ((unsigned int)moff_of(a.z) << 16)
                        | ((unsigned int)moff_of(a.w) << 24);
        ((unsigned int*)Mnext)[idx4] = mp;
    }
}

extern "C" void kernel_launch(void* const* d_in, const int* in_sizes, int n_in,
                              void* d_out, int out_size) {
    const float* x     = (const float*)d_in[0];
    const float* in_w0 = (const float*)d_in[1];
    const float* in_s0 = (const float*)d_in[2];
    const float* in_b0 = (const float*)d_in[3];
    const float* in_g0 = (const float*)d_in[4];
    const float* in_w1 = (const float*)d_in[5];
    const float* in_s1 = (const float*)d_in[6];
    const float* in_b1 = (const float*)d_in[7];
    const float* in_g1 = (const float*)d_in[8];
    const float* in_w2 = (const float*)d_in[9];
    const float* in_s2 = (const float*)d_in[10];
    const float* in_b2 = (const float*)d_in[11];
    const float* in_g2 = (const float*)d_in[12];
    float* out = (float*)d_out;

    void *pT0, *pS0, *pT1, *pS1, *pT2, *pS2;
    void *pA0, *pM0, *pA1, *pM1, *pA2, *pM2, *pPart;
    cudaGetSymbolAddress(&pT0, gT0); cudaGetSymbolAddress(&pS0, gS0);
    cudaGetSymbolAddress(&pT1, gT1); cudaGetSymbolAddress(&pS1, gS1);
    cudaGetSymbolAddress(&pT2, gT2); cudaGetSymbolAddress(&pS2, gS2);
    cudaGetSymbolAddress(&pA0, gA0); cudaGetSymbolAddress(&pM0, gM0);
    cudaGetSymbolAddress(&pA1, gA1); cudaGetSymbolAddress(&pM1, gM1);
    cudaGetSymbolAddress(&pA2, gA2); cudaGetSymbolAddress(&pM2, gM2);
    cudaGetSymbolAddress(&pPart, gPart);
    float* Pbuf = (float*)pPart;

    // fused: all 3 table precomputes + input activation
    setup_kernel<<<SETUP_TOTAL / 256, 256>>>(
        x,
        in_w0, in_s0, in_g0,
        in_w1, in_s1, in_g1,
        in_w2, in_s2, in_g2,
        (float*)pT0, (float*)pS0,
        (float*)pT1, (float*)pS1,
        (float*)pT2, (float*)pS2,
        (float*)pA0, (unsigned char*)pM0);

    // layer 0: 256x256 -> 256x512, split 2, IC 64 -> 1024 blocks
    layer_kernel<L0_IN, L0_OUT, 2, 64><<<dim3(L0_OUT / 16, BB / 16, 2), 256>>>(
        (const float*)pA0, (const unsigned char*)pM0,
        (const float*)pT0, (const float*)pS0, Pbuf);
    epi_kernel<L0_OUT, 2, false><<<BB * L0_OUT / 1024, 256>>>(
        Pbuf, in_b0, (float*)pA1, (unsigned char*)pM1, nullptr);

    // layer 1: 256x512 -> 256x256, split 4, IC 64 -> 1024 blocks
    layer_kernel<L1_IN, L1_OUT, 4, 64><<<dim3(L1_OUT / 16, BB / 16, 4), 256>>>(
        (const float*)pA1, (const unsigned char*)pM1,
        (const float*)pT1, (const float*)pS1, Pbuf);
    epi_kernel<L1_OUT, 4, false><<<BB * L1_OUT / 1024, 256>>>(
        Pbuf, in_b1, (float*)pA2, (unsigned char*)pM2, nullptr);

    // layer 2: 256x256 -> 256x128, split 8, IC 32 -> 1024 blocks
    layer_kernel<L2_IN, L2_OUT, 8, 32><<<dim3(L2_OUT / 16, BB / 16, 8), 256>>>(
        (const float*)pA2, (const unsigned char*)pM2,
        (const float*)pT2, (const float*)pS2, Pbuf);
    epi_kernel<L2_OUT, 8, true><<<BB * L2_OUT / 1024, 256>>>(
        Pbuf, in_b2, nullptr, nullptr, out);

    (void)in_sizes; (void)n_in; (void)out_size;
}

// round 7
// speedup vs baseline: 1.0786x; 1.0786x over previous
#include <cuda_runtime.h>
#include <math.h>

// KAN network: 3 layers, BATCH=256, dims 256->512->256->128, GRID=5
// Factorization: sum_k w_k * exp(-s*|a-g_k|) = exp(-s*a)*P_m + exp(s*a)*Q_m
//   m = #{k : g_k <= a}; P/Q prefix/suffix tables per (o,i), 8 floats each.
// R7: pq read directly from global T via __ldg (2 distinct 32B entries per
//     warp-instr -> L1 broadcast); smem only for A/m/S2 (~5KB). Removes the
//     T LDG->STS->LDS round-trip that was ~half of all L1tex wavefronts.

#define BB 256
#define GG 5

#define L0_IN 256
#define L0_OUT 512
#define L1_IN 512
#define L1_OUT 256
#define L2_IN 256
#define L2_OUT 128

static __device__ __constant__ float kLOG2E = 1.4426950408889634f;

// ---- scratch (device globals; no allocation allowed) ----
__device__ __align__(16) float gT0[L0_OUT * L0_IN * 8];
__device__ float gS0[L0_OUT * L0_IN];
__device__ __align__(16) float gT1[L1_OUT * L1_IN * 8];
__device__ float gS1[L1_OUT * L1_IN];
__device__ __align__(16) float gT2[L2_OUT * L2_IN * 8];
__device__ float gS2[L2_OUT * L2_IN];

__device__ float gA0[BB * L0_IN];
__device__ unsigned char gM0[BB * L0_IN];
__device__ float gA1[BB * L1_IN];
__device__ unsigned char gM1[BB * L1_IN];
__device__ float gA2[BB * L2_IN];
__device__ unsigned char gM2[BB * L2_IN];

// split-K partial sums: [split][b][o], max 8 x 256 x 128 / 4 x 256 x 512
__device__ float gPart[4 * BB * 512];

__device__ __forceinline__ float ex2f(float x) {
    float y;
    asm("ex2.approx.ftz.f32 %0, %1;" : "=f"(y) : "f"(x));
    return y;
}

__device__ __forceinline__ unsigned char moff_of(float a) {
    int m = (int)(a >= -0.5f) + (int)(a >= 0.f) + (int)(a >= 0.5f);
    return (unsigned char)(m * 8);  // byte offset into 8-float table entry
}

// per-(o,i) table: T[idx*8 + m*2] = P_{m+1}, T[idx*8 + m*2 + 1] = Q_{m+1}
__device__ __forceinline__ void precompute_one(
    int idx, const float* __restrict__ w, const float* __restrict__ s,
    const float* __restrict__ g, float* __restrict__ T, float* __restrict__ S2) {
    float s2 = __ldg(&s[idx]) * kLOG2E;
    S2[idx] = s2;
    float gk[GG], wk[GG];
#pragma unroll
    for (int k = 0; k < GG; k++) {
        gk[k] = __ldg(&g[k]);
        wk[k] = __ldg(&w[idx * GG + k]);
    }
    float q[GG + 1];
    q[GG] = 0.f;
#pragma unroll
    for (int k = GG - 1; k >= 0; k--)
        q[k] = q[k + 1] + wk[k] * ex2f(-s2 * gk[k]);
    float P = 0.f;
#pragma unroll
    for (int m = 1; m <= 4; m++) {
        P += wk[m - 1] * ex2f(s2 * gk[m - 1]);
        T[idx * 8 + (m - 1) * 2 + 0] = P;
        T[idx * 8 + (m - 1) * 2 + 1] = q[m];
    }
}

// ---- fused setup: 3 table precomputes + input activation ----
#define N_T0 (L0_OUT * L0_IN)
#define N_T1 (L1_OUT * L1_IN)
#define N_T2 (L2_OUT * L2_IN)
#define N_ACT (BB * L0_IN)
#define SETUP_TOTAL (N_T0 + N_T1 + N_T2 + N_ACT)

__global__ __launch_bounds__(256) void setup_kernel(
    const float* __restrict__ x,
    const float* __restrict__ w0, const float* __restrict__ s0, const float* __restrict__ g0,
    const float* __restrict__ w1, const float* __restrict__ s1, const float* __restrict__ g1,
    const float* __restrict__ w2, const float* __restrict__ s2, const float* __restrict__ g2,
    float* __restrict__ T0, float* __restrict__ S20,
    float* __restrict__ T1, float* __restrict__ S21,
    float* __restrict__ T2, float* __restrict__ S22,
    float* __restrict__ A0, unsigned char* __restrict__ M0) {
    int gid = blockIdx.x * 256 + threadIdx.x;
    if (gid < N_T0) {
        precompute_one(gid, w0, s0, g0, T0, S20);
    } else if (gid < N_T0 + N_T1) {
        precompute_one(gid - N_T0, w1, s1, g1, T1, S21);
    } else if (gid < N_T0 + N_T1 + N_T2) {
        precompute_one(gid - N_T0 - N_T1, w2, s2, g2, T2, S22);
    } else {
        int i = gid - N_T0 - N_T1 - N_T2;
        float a = tanhf(__ldg(&x[i]));
        A0[i] = a;
        M0[i] = moff_of(a);
    }
}

// ---- layer kernel (split-K): writes partial sum to P[split][b][o] ----
// Tile: BT=16 batch x OT=16 out, 256 threads, IC=32 i-chunk, grid.z = SPLIT.
// A/m/S2 staged in smem (i4-major, conflict-free); pq read via __ldg from T.
template <int IN, int OUT, int SPLIT>
__global__ __launch_bounds__(256) void layer_kernel(
    const float* __restrict__ A, const unsigned char* __restrict__ M,
    const float* __restrict__ T, const float* __restrict__ S2,
    float* __restrict__ P) {
    constexpr int BT = 16, OT = 16, IC = 32;
    constexpr int ILEN = IN / SPLIT;
    constexpr int NQ = IC / 4;  // 8 float4 quads per chunk row

    __shared__ float4 sA4[NQ][BT];
    __shared__ float4 sS4[NQ][OT];
    __shared__ unsigned int sMW[BT][NQ + 1];

    const int tid = threadIdx.x;
    const int bl = tid & 15;
    const int ol = tid >> 4;
    const int b0 = blockIdx.y * BT;
    const int o0 = blockIdx.x * OT;
    const int ibase = blockIdx.z * ILEN;

    // this thread's slice of T: entries for (o0+ol, ibase..): 32B per i
    const char* tband = (const char*)(T + (((size_t)(o0 + ol) * IN + ibase) << 3));

    float accP0 = 0.f, accP1 = 0.f, accQ0 = 0.f, accQ1 = 0.f;

#pragma unroll 1
    for (int ic = 0; ic < ILEN / IC; ic++) {
        const int i0 = ibase + ic * IC;
        __syncthreads();
        if (tid < 128) {
            int bb = tid >> 3, iq = tid & 7;
            sA4[iq][bb] = *(const float4*)&A[(b0 + bb) * IN + i0 + iq * 4];
            sMW[bb][iq] = ((const unsigned int*)(M + (b0 + bb) * IN + i0))[iq];
        } else {
            int u = tid - 128;
            int oo = u >> 3, iq = u & 7;
            sS4[iq][oo] = *(const float4*)&S2[(o0 + oo) * IN + i0 + iq * 4];
        }
        __syncthreads();

        const unsigned int* sMrow = sMW[bl];
        const char* cb = tband + (size_t)ic * IC * 32;

#pragma unroll
        for (int i4 = 0; i4 < NQ; i4++) {
            float4 av = sA4[i4][bl];
            float4 sv = sS4[i4][ol];
            unsigned int mw = sMrow[i4];
            const char* tb = cb + i4 * 128;

            // issue all 4 pq loads first (MLP), then math
            float2 pq0 = __ldg((const float2*)(tb + (mw & 0xFFu)));
            float2 pq1 = __ldg((const float2*)(tb + 32 + ((mw >> 8) & 0xFFu)));
            float2 pq2 = __ldg((const float2*)(tb + 64 + ((mw >> 16) & 0xFFu)));
            float2 pq3 = __ldg((const float2*)(tb + 96 + (mw >> 24)));

            float t0 = av.x * sv.x;
            accP0 = fmaf(ex2f(-t0), pq0.x, accP0);
            accQ0 = fmaf(ex2f(t0), pq0.y, accQ0);
            float t1 = av.y * sv.y;
            accP1 = fmaf(ex2f(-t1), pq1.x, accP1);
            accQ1 = fmaf(ex2f(t1), pq1.y, accQ1);
            float t2 = av.z * sv.z;
            accP0 = fmaf(ex2f(-t2), pq2.x, accP0);
            accQ0 = fmaf(ex2f(t2), pq2.y, accQ0);
            float t3 = av.w * sv.w;
            accP1 = fmaf(ex2f(-t3), pq3.x, accP1);
            accQ1 = fmaf(ex2f(t3), pq3.y, accQ1);
        }
    }

    P[(blockIdx.z * BB + b0 + bl) * OUT + o0 + ol] =
        (accP0 + accP1) + (accQ0 + accQ1);
}

// ---- epilogue: sum SPLIT partials + bias, activation (vectorized x4) ----
template <int OUT, int SPLIT, bool LAST>
__global__ __launch_bounds__(256) void epi_kernel(
    const float* __restrict__ P, const float* __restrict__ bias,
    float* __restrict__ Anext, unsigned char* __restrict__ Mnext,
    float* __restrict__ out) {
    int idx4 = blockIdx.x * 256 + threadIdx.x;   // float4 index, < BB*OUT/4
    int o4 = idx4 & (OUT / 4 - 1);
    float4 y = *(const float4*)&bias[o4 * 4];
#pragma unroll
    for (int s = 0; s < SPLIT; s++) {
        float4 p = *(const float4*)&P[s * BB * OUT + idx4 * 4];
        y.x += p.x; y.y += p.y; y.z += p.z; y.w += p.w;
    }
    if (LAST) {
        float4 r;
        r.x = tanhf(y.x); r.y = tanhf(y.y); r.z = tanhf(y.z); r.w = tanhf(y.w);
        *(float4*)&out[idx4 * 4] = r;
    } else {
        float4 a;
        a.x = (y.x > 0.f) ? tanhf(y.x) : 0.f;
        a.y = (y.y > 0.f) ? tanhf(y.y) : 0.f;
        a.z = (y.z > 0.f) ? tanhf(y.z) : 0.f;
        a.w = (y.w > 0.f) ? tanhf(y.w) : 0.f;
        *(float4*)&Anext[idx4 * 4] = a;
        unsigned int mp = (unsigned int)moff_of(a.x)
                        | ((unsigned int)moff_of(a.y) << 8)
                        | ((unsigned int)moff_of(a.z) << 16)
                        | ((unsigned int)moff_of(a.w) << 24);
        ((unsigned int*)Mnext)[idx4] = mp;
    }
}

extern "C" void kernel_launch(void* const* d_in, const int* in_sizes, int n_in,
                              void* d_out, int out_size) {
    const float* x     = (const float*)d_in[0];
    const float* in_w0 = (const float*)d_in[1];
    const float* in_s0 = (const float*)d_in[2];
    const float* in_b0 = (const float*)d_in[3];
    const float* in_g0 = (const float*)d_in[4];
    const float* in_w1 = (const float*)d_in[5];
    const float* in_s1 = (const float*)d_in[6];
    const float* in_b1 = (const float*)d_in[7];
    const float* in_g1 = (const float*)d_in[8];
    const float* in_w2 = (const float*)d_in[9];
    const float* in_s2 = (const float*)d_in[10];
    const float* in_b2 = (const float*)d_in[11];
    const float* in_g2 = (const float*)d_in[12];
    float* out = (float*)d_out;

    void *pT0, *pS0, *pT1, *pS1, *pT2, *pS2;
    void *pA0, *pM0, *pA1, *pM1, *pA2, *pM2, *pPart;
    cudaGetSymbolAddress(&pT0, gT0); cudaGetSymbolAddress(&pS0, gS0);
    cudaGetSymbolAddress(&pT1, gT1); cudaGetSymbolAddress(&pS1, gS1);
    cudaGetSymbolAddress(&pT2, gT2); cudaGetSymbolAddress(&pS2, gS2);
    cudaGetSymbolAddress(&pA0, gA0); cudaGetSymbolAddress(&pM0, gM0);
    cudaGetSymbolAddress(&pA1, gA1); cudaGetSymbolAddress(&pM1, gM1);
    cudaGetSymbolAddress(&pA2, gA2); cudaGetSymbolAddress(&pM2, gM2);
    cudaGetSymbolAddress(&pPart, gPart);
    float* Pbuf = (float*)pPart;

    // fused: all 3 table precomputes + input activation
    setup_kernel<<<SETUP_TOTAL / 256, 256>>>(
        x,
        in_w0, in_s0, in_g0,
        in_w1, in_s1, in_g1,
        in_w2, in_s2, in_g2,
        (float*)pT0, (float*)pS0,
        (float*)pT1, (float*)pS1,
        (float*)pT2, (float*)pS2,
        (float*)pA0, (unsigned char*)pM0);

    // layer 0: 256x256 -> 256x512, split 2 -> 1024 blocks
    layer_kernel<L0_IN, L0_OUT, 2><<<dim3(L0_OUT / 16, BB / 16, 2), 256>>>(
        (const float*)pA0, (const unsigned char*)pM0,
        (const float*)pT0, (const float*)pS0, Pbuf);
    epi_kernel<L0_OUT, 2, false><<<BB * L0_OUT / 1024, 256>>>(
        Pbuf, in_b0, (float*)pA1, (unsigned char*)pM1, nullptr);

    // layer 1: 256x512 -> 256x256, split 4 -> 1024 blocks
    layer_kernel<L1_IN, L1_OUT, 4><<<dim3(L1_OUT / 16, BB / 16, 4), 256>>>(
        (const float*)pA1, (const unsigned char*)pM1,
        (const float*)pT1, (const float*)pS1, Pbuf);
    epi_kernel<L1_OUT, 4, false><<<BB * L1_OUT / 1024, 256>>>(
        Pbuf, in_b1, (float*)pA2, (unsigned char*)pM2, nullptr);

    // layer 2: 256x256 -> 256x128, split 8 -> 1024 blocks
    layer_kernel<L2_IN, L2_OUT, 8><<<dim3(L2_OUT / 16, BB / 16, 8), 256>>>(
        (const float*)pA2, (const unsigned char*)pM2,
        (const float*)pT2, (const float*)pS2, Pbuf);
    epi_kernel<L2_OUT, 8, true><<<BB * L2_OUT / 1024, 256>>>(
        Pbuf, in_b2, nullptr, nullptr, out);

    (void)in_sizes; (void)n_in; (void)out_size;
}

// round 8
// speedup vs baseline: 1.2064x; 1.1185x over previous
#include <cuda_runtime.h>
#include <math.h>

// KAN network: 3 layers, BATCH=256, dims 256->512->256->128, GRID=5
// Factorization: sum_k w_k * exp(-s*|a-g_k|) = exp(-s*a)*P_m + exp(s*a)*Q_m
//   m = #{k : g_k <= a}; P/Q prefix/suffix tables per (o,i), 8 floats each.
// R8: depth-3 software pipeline on the pq LDGs (ring of 4 groups, ~16 loads
//     in flight) + register-staged A/S2 prefetch across chunks + higher
//     split-K (2048-block grids). Goal: hide ~250cyc L2 latency, drive issue
//     to the MUFU-saturation point (~55%).

#define BB 256
#define GG 5

#define L0_IN 256
#define L0_OUT 512
#define L1_IN 512
#define L1_OUT 256
#define L2_IN 256
#define L2_OUT 128

static __device__ __constant__ float kLOG2E = 1.4426950408889634f;

// ---- scratch (device globals; no allocation allowed) ----
__device__ __align__(16) float gT0[L0_OUT * L0_IN * 8];
__device__ float gS0[L0_OUT * L0_IN];
__device__ __align__(16) float gT1[L1_OUT * L1_IN * 8];
__device__ float gS1[L1_OUT * L1_IN];
__device__ __align__(16) float gT2[L2_OUT * L2_IN * 8];
__device__ float gS2[L2_OUT * L2_IN];

__device__ float gA0[BB * L0_IN];
__device__ unsigned char gM0[BB * L0_IN];
__device__ float gA1[BB * L1_IN];
__device__ unsigned char gM1[BB * L1_IN];
__device__ float gA2[BB * L2_IN];
__device__ unsigned char gM2[BB * L2_IN];

// split-K partial sums: [split][b][o]; max = 4x256x512 = 8x256x256 = 512K floats
__device__ float gPart[4 * BB * 512];

__device__ __forceinline__ float ex2f(float x) {
    float y;
    asm("ex2.approx.ftz.f32 %0, %1;" : "=f"(y) : "f"(x));
    return y;
}

__device__ __forceinline__ unsigned char moff_of(float a) {
    int m = (int)(a >= -0.5f) + (int)(a >= 0.f) + (int)(a >= 0.5f);
    return (unsigned char)(m * 8);  // byte offset into 8-float table entry
}

// per-(o,i) table: T[idx*8 + m*2] = P_{m+1}, T[idx*8 + m*2 + 1] = Q_{m+1}
__device__ __forceinline__ void precompute_one(
    int idx, const float* __restrict__ w, const float* __restrict__ s,
    const float* __restrict__ g, float* __restrict__ T, float* __restrict__ S2) {
    float s2 = __ldg(&s[idx]) * kLOG2E;
    S2[idx] = s2;
    float gk[GG], wk[GG];
#pragma unroll
    for (int k = 0; k < GG; k++) {
        gk[k] = __ldg(&g[k]);
        wk[k] = __ldg(&w[idx * GG + k]);
    }
    float q[GG + 1];
    q[GG] = 0.f;
#pragma unroll
    for (int k = GG - 1; k >= 0; k--)
        q[k] = q[k + 1] + wk[k] * ex2f(-s2 * gk[k]);
    float P = 0.f;
#pragma unroll
    for (int m = 1; m <= 4; m++) {
        P += wk[m - 1] * ex2f(s2 * gk[m - 1]);
        T[idx * 8 + (m - 1) * 2 + 0] = P;
        T[idx * 8 + (m - 1) * 2 + 1] = q[m];
    }
}

// ---- fused setup: 3 table precomputes + input activation ----
#define N_T0 (L0_OUT * L0_IN)
#define N_T1 (L1_OUT * L1_IN)
#define N_T2 (L2_OUT * L2_IN)
#define N_ACT (BB * L0_IN)
#define SETUP_TOTAL (N_T0 + N_T1 + N_T2 + N_ACT)

__global__ __launch_bounds__(256) void setup_kernel(
    const float* __restrict__ x,
    const float* __restrict__ w0, const float* __restrict__ s0, const float* __restrict__ g0,
    const float* __restrict__ w1, const float* __restrict__ s1, const float* __restrict__ g1,
    const float* __restrict__ w2, const float* __restrict__ s2, const float* __restrict__ g2,
    float* __restrict__ T0, float* __restrict__ S20,
    float* __restrict__ T1, float* __restrict__ S21,
    float* __restrict__ T2, float* __restrict__ S22,
    float* __restrict__ A0, unsigned char* __restrict__ M0) {
    int gid = blockIdx.x * 256 + threadIdx.x;
    if (gid < N_T0) {
        precompute_one(gid, w0, s0, g0, T0, S20);
    } else if (gid < N_T0 + N_T1) {
        precompute_one(gid - N_T0, w1, s1, g1, T1, S21);
    } else if (gid < N_T0 + N_T1 + N_T2) {
        precompute_one(gid - N_T0 - N_T1, w2, s2, g2, T2, S22);
    } else {
        int i = gid - N_T0 - N_T1 - N_T2;
        float a = tanhf(__ldg(&x[i]));
        A0[i] = a;
        M0[i] = moff_of(a);
    }
}

// load one pq group (4 entries, 32B apart, per-element m offset)
__device__ __forceinline__ void ldgrp(float2* d, const char* tb, unsigned int mw) {
    d[0] = __ldg((const float2*)(tb + (mw & 0xFFu)));
    d[1] = __ldg((const float2*)(tb + 32 + ((mw >> 8) & 0xFFu)));
    d[2] = __ldg((const float2*)(tb + 64 + ((mw >> 16) & 0xFFu)));
    d[3] = __ldg((const float2*)(tb + 96 + (mw >> 24)));
}

// ---- layer kernel (split-K): writes partial sum to P[split][b][o] ----
// BT=16 x OT=16, 256 threads, IC=32, grid.z = SPLIT.
// A/m/S2 in smem (register-prefetched across chunks); pq via pipelined __ldg.
template <int IN, int OUT, int SPLIT>
__global__ __launch_bounds__(256) void layer_kernel(
    const float* __restrict__ A, const unsigned char* __restrict__ M,
    const float* __restrict__ T, const float* __restrict__ S2,
    float* __restrict__ P) {
    constexpr int BT = 16, OT = 16, IC = 32;
    constexpr int ILEN = IN / SPLIT;
    constexpr int NQ = IC / 4;          // 8 groups per chunk
    constexpr int NCHUNK = ILEN / IC;

    __shared__ float4 sA4[NQ][BT];
    __shared__ float4 sS4[NQ][OT];
    __shared__ unsigned int sMW[BT][NQ + 1];

    const int tid = threadIdx.x;
    const int bl = tid & 15;
    const int ol = tid >> 4;
    const int b0 = blockIdx.y * BT;
    const int o0 = blockIdx.x * OT;
    const int ibase = blockIdx.z * ILEN;

    // this thread's T band: entries for (o0+ol, ibase..), 32B per i
    const char* tband = (const char*)(T + (((size_t)(o0 + ol) * IN + ibase) << 3));

    // staging identity (fixed per thread)
    const int ldRow = (tid & 127) >> 3;   // bb or oo
    const int ldIQ = tid & 7;

    // prologue: load chunk 0 into registers
    float4 rV;
    unsigned int rM = 0;
    if (tid < 128) {
        rV = *(const float4*)&A[(b0 + ldRow) * IN + ibase + ldIQ * 4];
        rM = ((const unsigned int*)(M + (b0 + ldRow) * IN + ibase))[ldIQ];
    } else {
        rV = *(const float4*)&S2[(o0 + ldRow) * IN + ibase + ldIQ * 4];
    }

    float accP0 = 0.f, accP1 = 0.f, accQ0 = 0.f, accQ1 = 0.f;

#pragma unroll
    for (int c = 0; c < NCHUNK; c++) {
        __syncthreads();   // previous chunk's compute done (no-op cost at c=0)
        if (tid < 128) {
            sA4[ldIQ][ldRow] = rV;
            sMW[ldRow][ldIQ] = rM;
        } else {
            sS4[ldIQ][ldRow] = rV;
        }
        // prefetch next chunk while this chunk computes
        if (c + 1 < NCHUNK) {
            const int i0n = ibase + (c + 1) * IC;
            if (tid < 128) {
                rV = *(const float4*)&A[(b0 + ldRow) * IN + i0n + ldIQ * 4];
                rM = ((const unsigned int*)(M + (b0 + ldRow) * IN + i0n))[ldIQ];
            } else {
                rV = *(const float4*)&S2[(o0 + ldRow) * IN + i0n + ldIQ * 4];
            }
        }
        __syncthreads();

        const unsigned int* sMrow = sMW[bl];
        const char* cb = tband + (size_t)c * IC * 32;

        // read all m-words for this chunk
        unsigned int mwA[NQ];
#pragma unroll
        for (int q = 0; q < NQ; q++) mwA[q] = sMrow[q];

        // depth-3 pq pipeline, ring of 4 groups
        float2 pqb[4][4];
#pragma unroll
        for (int p = 0; p < 3; p++) ldgrp(pqb[p], cb + p * 128, mwA[p]);

#pragma unroll
        for (int i4 = 0; i4 < NQ; i4++) {
            if (i4 + 3 < NQ)
                ldgrp(pqb[(i4 + 3) & 3], cb + (i4 + 3) * 128, mwA[i4 + 3]);
            float4 av = sA4[i4][bl];
            float4 sv = sS4[i4][ol];
            const float2* pq = pqb[i4 & 3];

            float t0 = av.x * sv.x;
            accP0 = fmaf(ex2f(-t0), pq[0].x, accP0);
            accQ0 = fmaf(ex2f(t0), pq[0].y, accQ0);
            float t1 = av.y * sv.y;
            accP1 = fmaf(ex2f(-t1), pq[1].x, accP1);
            accQ1 = fmaf(ex2f(t1), pq[1].y, accQ1);
            float t2 = av.z * sv.z;
            accP0 = fmaf(ex2f(-t2), pq[2].x, accP0);
            accQ0 = fmaf(ex2f(t2), pq[2].y, accQ0);
            float t3 = av.w * sv.w;
            accP1 = fmaf(ex2f(-t3), pq[3].x, accP1);
            accQ1 = fmaf(ex2f(t3), pq[3].y, accQ1);
        }
    }

    P[(blockIdx.z * BB + b0 + bl) * OUT + o0 + ol] =
        (accP0 + accP1) + (accQ0 + accQ1);
}

// ---- epilogue: sum SPLIT partials + bias, activation (vectorized x4) ----
template <int OUT, int SPLIT, bool LAST>
__global__ __launch_bounds__(256) void epi_kernel(
    const float* __restrict__ P, const float* __restrict__ bias,
    float* __restrict__ Anext, unsigned char* __restrict__ Mnext,
    float* __restrict__ out) {
    int idx4 = blockIdx.x * 256 + threadIdx.x;   // float4 index, < BB*OUT/4
    int o4 = idx4 & (OUT / 4 - 1);
    float4 y = *(const float4*)&bias[o4 * 4];
#pragma unroll
    for (int s = 0; s < SPLIT; s++) {
        float4 p = *(const float4*)&P[s * BB * OUT + idx4 * 4];
        y.x += p.x; y.y += p.y; y.z += p.z; y.w += p.w;
    }
    if (LAST) {
        float4 r;
        r.x = tanhf(y.x); r.y = tanhf(y.y); r.z = tanhf(y.z); r.w = tanhf(y.w);
        *(float4*)&out[idx4 * 4] = r;
    } else {
        float4 a;
        a.x = (y.x > 0.f) ? tanhf(y.x) : 0.f;
        a.y = (y.y > 0.f) ? tanhf(y.y) : 0.f;
        a.z = (y.z > 0.f) ? tanhf(y.z) : 0.f;
        a.w = (y.w > 0.f) ? tanhf(y.w) : 0.f;
        *(float4*)&Anext[idx4 * 4] = a;
        unsigned int mp = (unsigned int)moff_of(a.x)
                        | ((unsigned int)moff_of(a.y) << 8)
                        | ((unsigned int)moff_of(a.z) << 16)
                        | ((unsigned int)moff_of(a.w) << 24);
        ((unsigned int*)Mnext)[idx4] = mp;
    }
}

extern "C" void kernel_launch(void* const* d_in, const int* in_sizes, int n_in,
                              void* d_out, int out_size) {
    const float* x     = (const float*)d_in[0];
    const float* in_w0 = (const float*)d_in[1];
    const float* in_s0 = (const float*)d_in[2];
    const float* in_b0 = (const float*)d_in[3];
    const float* in_g0 = (const float*)d_in[4];
    const float* in_w1 = (const float*)d_in[5];
    const float* in_s1 = (const float*)d_in[6];
    const float* in_b1 = (const float*)d_in[7];
    const float* in_g1 = (const float*)d_in[8];
    const float* in_w2 = (const float*)d_in[9];
    const float* in_s2 = (const float*)d_in[10];
    const float* in_b2 = (const float*)d_in[11];
    const float* in_g2 = (const float*)d_in[12];
    float* out = (float*)d_out;

    void *pT0, *pS0, *pT1, *pS1, *pT2, *pS2;
    void *pA0, *pM0, *pA1, *pM1, *pA2, *pM2, *pPart;
    cudaGetSymbolAddress(&pT0, gT0); cudaGetSymbolAddress(&pS0, gS0);
    cudaGetSymbolAddress(&pT1, gT1); cudaGetSymbolAddress(&pS1, gS1);
    cudaGetSymbolAddress(&pT2, gT2); cudaGetSymbolAddress(&pS2, gS2);
    cudaGetSymbolAddress(&pA0, gA0); cudaGetSymbolAddress(&pM0, gM0);
    cudaGetSymbolAddress(&pA1, gA1); cudaGetSymbolAddress(&pM1, gM1);
    cudaGetSymbolAddress(&pA2, gA2); cudaGetSymbolAddress(&pM2, gM2);
    cudaGetSymbolAddress(&pPart, gPart);
    float* Pbuf = (float*)pPart;

    // fused: all 3 table precomputes + input activation
    setup_kernel<<<SETUP_TOTAL / 256, 256>>>(
        x,
        in_w0, in_s0, in_g0,
        in_w1, in_s1, in_g1,
        in_w2, in_s2, in_g2,
        (float*)pT0, (float*)pS0,
        (float*)pT1, (float*)pS1,
        (float*)pT2, (float*)pS2,
        (float*)pA0, (unsigned char*)pM0);

    // layer 0: 256x256 -> 256x512, split 4 -> 2048 blocks (ILEN 64)
    layer_kernel<L0_IN, L0_OUT, 4><<<dim3(L0_OUT / 16, BB / 16, 4), 256>>>(
        (const float*)pA0, (const unsigned char*)pM0,
        (const float*)pT0, (const float*)pS0, Pbuf);
    epi_kernel<L0_OUT, 4, false><<<BB * L0_OUT / 1024, 256>>>(
        Pbuf, in_b0, (float*)pA1, (unsigned char*)pM1, nullptr);

    // layer 1: 256x512 -> 256x256, split 8 -> 2048 blocks (ILEN 64)
    layer_kernel<L1_IN, L1_OUT, 8><<<dim3(L1_OUT / 16, BB / 16, 8), 256>>>(
        (const float*)pA1, (const unsigned char*)pM1,
        (const float*)pT1, (const float*)pS1, Pbuf);
    epi_kernel<L1_OUT, 8, false><<<BB * L1_OUT / 1024, 256>>>(
        Pbuf, in_b1, (float*)pA2, (unsigned char*)pM2, nullptr);

    // layer 2: 256x256 -> 256x128, split 8 -> 1024 blocks (ILEN 32)
    layer_kernel<L2_IN, L2_OUT, 8><<<dim3(L2_OUT / 16, BB / 16, 8), 256>>>(
        (const float*)pA2, (const unsigned char*)pM2,
        (const float*)pT2, (const float*)pS2, Pbuf);
    epi_kernel<L2_OUT, 8, true><<<BB * L2_OUT / 1024, 256>>>(
        Pbuf, in_b2, nullptr, nullptr, out);

    (void)in_sizes; (void)n_in; (void)out_size;
}